// round 1
// baseline (speedup 1.0000x reference)
#include <cuda_runtime.h>

#define NT   2048
#define FEAT 768
#define NH   12
#define DH   64

// Scratch (device globals — no allocation allowed)
__device__ float g_Q[NT * FEAT];
__device__ float g_K[NT * FEAT];
__device__ float g_V[NT * FEAT];
__device__ float g_A[NT * FEAT];
__device__ float g_Y[NT * FEAT];

// ---------------------------------------------------------------------------
// C[m][n] = sum_k A[m][k] * B[n][k]  (+ R[m][n] if R != nullptr)
// A: [M,K] row-major, B: [N,K] row-major (i.e. C = A @ B^T)
// Tiles: 64x64 output per block, BK=16, 256 threads, 4x4 microtile.
// ---------------------------------------------------------------------------
__global__ __launch_bounds__(256) void gemm_nt(const float* __restrict__ A,
                                               const float* __restrict__ B,
                                               const float* __restrict__ R,
                                               float* __restrict__ C,
                                               int M, int N, int K)
{
    const int BM = 64, BK = 16, PITCH = 68;  // pitch 68 floats: float4-aligned rows
    __shared__ float As[BK][PITCH];
    __shared__ float Bs[BK][PITCH];

    int tid = threadIdx.x;
    int tx = tid & 15;        // 0..15 -> output cols tx*4..tx*4+3
    int ty = tid >> 4;        // 0..15 -> output rows ty*4..ty*4+3
    int bm = blockIdx.y * BM;
    int bn = blockIdx.x * BM;

    float acc[4][4] = {};

    for (int k0 = 0; k0 < K; k0 += BK) {
        // Load A and B tiles: 64x16 each, k-contiguous global reads.
#pragma unroll
        for (int i = 0; i < 4; i++) {
            int idx = tid + i * 256;   // 0..1023
            int m  = idx >> 4;         // row within tile
            int kk = idx & 15;         // k within tile
            As[kk][m] = A[(size_t)(bm + m) * K + k0 + kk];
            Bs[kk][m] = B[(size_t)(bn + m) * K + k0 + kk];
        }
        __syncthreads();

#pragma unroll
        for (int kk = 0; kk < BK; kk++) {
            float4 a4 = *(const float4*)&As[kk][ty * 4];
            float4 b4 = *(const float4*)&Bs[kk][tx * 4];
            float av[4] = {a4.x, a4.y, a4.z, a4.w};
            float bv[4] = {b4.x, b4.y, b4.z, b4.w};
#pragma unroll
            for (int i = 0; i < 4; i++)
#pragma unroll
                for (int j = 0; j < 4; j++)
                    acc[i][j] += av[i] * bv[j];
        }
        __syncthreads();
    }

#pragma unroll
    for (int i = 0; i < 4; i++) {
        int m = bm + ty * 4 + i;
        size_t off = (size_t)m * N + bn + tx * 4;
        float4 c4 = make_float4(acc[i][0], acc[i][1], acc[i][2], acc[i][3]);
        if (R) {
            float4 r4 = *(const float4*)&R[off];
            c4.x += r4.x; c4.y += r4.y; c4.z += r4.z; c4.w += r4.w;
        }
        *(float4*)&C[off] = c4;
    }
}

// ---------------------------------------------------------------------------
// Flash-style attention, fp32, online softmax.
// grid: (NT/64, NH). block: 256 threads = 8 warps.
// Each block: 64 query rows for one head. Key tiles of 32.
// Warp w owns query rows w*8 .. w*8+7. Lane owns score col = lane (of 32),
// and output head-dims {lane, lane+32}.
// Q is prescaled by 1/8 (= 1/sqrt(64), exact in fp32).
// ---------------------------------------------------------------------------
__global__ __launch_bounds__(256) void flash_attn(const float* __restrict__ Q,
                                                  const float* __restrict__ K,
                                                  const float* __restrict__ V,
                                                  float* __restrict__ O)
{
    const int KT = 32;
    __shared__ float Qs[64][64];
    __shared__ float Ks[KT][68];   // padded, float4-aligned rows
    __shared__ float Vs[KT][64];
    __shared__ float Ps[64][KT];

    int h  = blockIdx.y;
    int q0 = blockIdx.x * 64;
    int tid = threadIdx.x, warp = tid >> 5, lane = tid & 31;

    // Load + prescale Q tile
    for (int i = tid; i < 64 * 64; i += 256) {
        int r = i >> 6, c = i & 63;
        Qs[r][c] = Q[(size_t)(q0 + r) * FEAT + h * DH + c] * 0.125f;
    }

    float m[8], l[8], acc0[8], acc1[8];
#pragma unroll
    for (int r = 0; r < 8; r++) { m[r] = -1e30f; l[r] = 0.f; acc0[r] = 0.f; acc1[r] = 0.f; }

    for (int k0 = 0; k0 < NT; k0 += KT) {
        __syncthreads();   // previous-tile readers done (also orders Qs on iter 0)
        for (int i = tid; i < KT * 64; i += 256) {
            int r = i >> 6, c = i & 63;
            Ks[r][c] = K[(size_t)(k0 + r) * FEAT + h * DH + c];
            Vs[r][c] = V[(size_t)(k0 + r) * FEAT + h * DH + c];
        }
        __syncthreads();

        // Scores: s[r] = Qrow . Kcol(lane)
        float s[8];
#pragma unroll
        for (int r = 0; r < 8; r++) s[r] = 0.f;
#pragma unroll
        for (int i4 = 0; i4 < 16; i4++) {
            float4 kv = *(const float4*)&Ks[lane][i4 * 4];
#pragma unroll
            for (int r = 0; r < 8; r++) {
                float4 qv = *(const float4*)&Qs[warp * 8 + r][i4 * 4];
                s[r] += qv.x * kv.x + qv.y * kv.y + qv.z * kv.z + qv.w * kv.w;
            }
        }

        // Online softmax per row (reduction across 32 lanes = 32 key cols)
#pragma unroll
        for (int r = 0; r < 8; r++) {
            int row = warp * 8 + r;
            float mx = s[r];
#pragma unroll
            for (int o = 16; o; o >>= 1) mx = fmaxf(mx, __shfl_xor_sync(0xffffffffu, mx, o));
            float mn   = fmaxf(m[r], mx);
            float corr = __expf(m[r] - mn);
            float p    = __expf(s[r] - mn);
            float ps   = p;
#pragma unroll
            for (int o = 16; o; o >>= 1) ps += __shfl_xor_sync(0xffffffffu, ps, o);
            l[r] = l[r] * corr + ps;
            m[r] = mn;
            acc0[r] *= corr;
            acc1[r] *= corr;
            Ps[row][lane] = p;
        }
        __syncwarp();

        // O += P @ V  (reuse each V element across the warp's 8 rows)
#pragma unroll 4
        for (int k = 0; k < KT; k++) {
            float v0 = Vs[k][lane];
            float v1 = Vs[k][lane + 32];
#pragma unroll
            for (int r = 0; r < 8; r++) {
                float p = Ps[warp * 8 + r][k];
                acc0[r] += p * v0;
                acc1[r] += p * v1;
            }
        }
    }

#pragma unroll
    for (int r = 0; r < 8; r++) {
        int row = q0 + warp * 8 + r;
        float inv = 1.0f / l[r];
        O[(size_t)row * FEAT + h * DH + lane]      = acc0[r] * inv;
        O[(size_t)row * FEAT + h * DH + lane + 32] = acc1[r] * inv;
    }
}

// ---------------------------------------------------------------------------
// Row LayerNorm: out = (y - mu)/sqrt(var + 1e-12) * gamma + beta
// One block per row, 256 threads, 3 elems/thread.
// ---------------------------------------------------------------------------
__global__ __launch_bounds__(256) void ln_kernel(const float* __restrict__ Y,
                                                 const float* __restrict__ gamma,
                                                 const float* __restrict__ beta,
                                                 float* __restrict__ out)
{
    int row = blockIdx.x;
    const float* y = Y + (size_t)row * FEAT;
    int tid = threadIdx.x, warp = tid >> 5, lane = tid & 31;

    float v[3];
    float s = 0.f, ss = 0.f;
#pragma unroll
    for (int i = 0; i < 3; i++) {
        v[i] = y[tid + i * 256];
        s  += v[i];
        ss += v[i] * v[i];
    }
#pragma unroll
    for (int o = 16; o; o >>= 1) {
        s  += __shfl_xor_sync(0xffffffffu, s, o);
        ss += __shfl_xor_sync(0xffffffffu, ss, o);
    }

    __shared__ float rs[8], rss[8];
    if (lane == 0) { rs[warp] = s; rss[warp] = ss; }
    __syncthreads();
    if (warp == 0) {
        float a = (lane < 8) ? rs[lane]  : 0.f;
        float b = (lane < 8) ? rss[lane] : 0.f;
#pragma unroll
        for (int o = 4; o; o >>= 1) {
            a += __shfl_xor_sync(0xffffffffu, a, o);
            b += __shfl_xor_sync(0xffffffffu, b, o);
        }
        if (lane == 0) { rs[0] = a; rss[0] = b; }
    }
    __syncthreads();

    float mu   = rs[0] * (1.0f / FEAT);
    float var  = rss[0] * (1.0f / FEAT) - mu * mu;
    float rstd = rsqrtf(var + 1e-12f);
#pragma unroll
    for (int i = 0; i < 3; i++) {
        int c = tid + i * 256;
        out[(size_t)row * FEAT + c] = (v[i] - mu) * rstd * gamma[c] + beta[c];
    }
}

// ---------------------------------------------------------------------------

extern "C" void kernel_launch(void* const* d_in, const int* in_sizes, int n_in,
                              void* d_out, int out_size)
{
    const float* x     = (const float*)d_in[0];
    const float* Wq    = (const float*)d_in[1];
    const float* Wk    = (const float*)d_in[2];
    const float* Wv    = (const float*)d_in[3];
    const float* Wo    = (const float*)d_in[4];
    const float* gamma = (const float*)d_in[5];
    const float* beta  = (const float*)d_in[6];
    float* out = (float*)d_out;

    float *pQ, *pK, *pV, *pA, *pY;
    cudaGetSymbolAddress((void**)&pQ, g_Q);
    cudaGetSymbolAddress((void**)&pK, g_K);
    cudaGetSymbolAddress((void**)&pV, g_V);
    cudaGetSymbolAddress((void**)&pA, g_A);
    cudaGetSymbolAddress((void**)&pY, g_Y);

    dim3 gg(FEAT / 64, NT / 64);   // (12, 32)
    gemm_nt<<<gg, 256>>>(x, Wq, nullptr, pQ, NT, FEAT, FEAT);
    gemm_nt<<<gg, 256>>>(x, Wk, nullptr, pK, NT, FEAT, FEAT);
    gemm_nt<<<gg, 256>>>(x, Wv, nullptr, pV, NT, FEAT, FEAT);

    flash_attn<<<dim3(NT / 64, NH), 256>>>(pQ, pK, pV, pA);

    gemm_nt<<<gg, 256>>>(pA, Wo, x, pY, NT, FEAT, FEAT);   // + residual

    ln_kernel<<<NT, 256>>>(pY, gamma, beta, out);
}

// round 2
// speedup vs baseline: 2.9892x; 2.9892x over previous
#include <cuda_runtime.h>
#include <cuda_bf16.h>
#include <cstdint>

#define NT   2048
#define FEAT 768
#define NH   12
#define DH   64

// Scratch (device globals; no allocation allowed)
__device__ __nv_bfloat16 g_Qh[NT * FEAT];
__device__ __nv_bfloat16 g_Ql[NT * FEAT];
__device__ __nv_bfloat16 g_Kh[NT * FEAT];
__device__ __nv_bfloat16 g_Kl[NT * FEAT];
__device__ __nv_bfloat16 g_Vh[NT * FEAT];
__device__ __nv_bfloat16 g_Vl[NT * FEAT];
__device__ float g_A[NT * FEAT];
__device__ float g_Y[NT * FEAT];

// ---------------------------------------------------------------------------
// PTX helpers
// ---------------------------------------------------------------------------
__device__ __forceinline__ uint32_t smem_u32(const void* p) {
    uint32_t a;
    asm("{ .reg .u64 t; cvta.to.shared.u64 t, %1; cvt.u32.u64 %0, t; }" : "=r"(a) : "l"(p));
    return a;
}
__device__ __forceinline__ void ldmx4(uint32_t* r, uint32_t addr) {
    asm volatile("ldmatrix.sync.aligned.m8n8.x4.shared.b16 {%0,%1,%2,%3}, [%4];"
                 : "=r"(r[0]), "=r"(r[1]), "=r"(r[2]), "=r"(r[3]) : "r"(addr));
}
__device__ __forceinline__ void ldmx4t(uint32_t* r, uint32_t addr) {
    asm volatile("ldmatrix.sync.aligned.m8n8.x4.trans.shared.b16 {%0,%1,%2,%3}, [%4];"
                 : "=r"(r[0]), "=r"(r[1]), "=r"(r[2]), "=r"(r[3]) : "r"(addr));
}
__device__ __forceinline__ void mma16816(float* c, const uint32_t* a, const uint32_t* b) {
    asm volatile(
        "mma.sync.aligned.m16n8k16.row.col.f32.bf16.bf16.f32 "
        "{%0,%1,%2,%3}, {%4,%5,%6,%7}, {%8,%9}, {%0,%1,%2,%3};"
        : "+f"(c[0]), "+f"(c[1]), "+f"(c[2]), "+f"(c[3])
        : "r"(a[0]), "r"(a[1]), "r"(a[2]), "r"(a[3]), "r"(b[0]), "r"(b[1]));
}

// split fp32 -> (hi, lo) bf16 packed pairs
__device__ __forceinline__ uint32_t pack2(__nv_bfloat16 a, __nv_bfloat16 b) {
    return (uint32_t)__bfloat16_as_ushort(a) | ((uint32_t)__bfloat16_as_ushort(b) << 16);
}
__device__ __forceinline__ void split2(float x, float y, uint32_t& h, uint32_t& l) {
    __nv_bfloat16 hx = __float2bfloat16(x), hy = __float2bfloat16(y);
    __nv_bfloat16 lx = __float2bfloat16(x - __bfloat162float(hx));
    __nv_bfloat16 ly = __float2bfloat16(y - __bfloat162float(hy));
    h = pack2(hx, hy);
    l = pack2(lx, ly);
}
__device__ __forceinline__ void split4(float4 v, uint2& h, uint2& l) {
    uint32_t h0, l0, h1, l1;
    split2(v.x, v.y, h0, l0);
    split2(v.z, v.w, h1, l1);
    h = make_uint2(h0, h1);
    l = make_uint2(l0, l1);
}

// ---------------------------------------------------------------------------
// GEMM: C[m][n] = sum_k A[m][k]*B[n][k]  via bf16-split mma (3 products).
// Block 64x64, BK=32, 128 threads (4 warps, 2x2 warp grid, 32x32 warp tiles).
// SPLIT_OUT: write Chi/Clo bf16; else write fp32 C (+R residual).
// ---------------------------------------------------------------------------
template <bool SPLIT_OUT>
__global__ __launch_bounds__(128) void gemm_mma(
    const float* __restrict__ A, const float* __restrict__ B,
    const float* __restrict__ R, float* __restrict__ C,
    __nv_bfloat16* __restrict__ Chi, __nv_bfloat16* __restrict__ Clo,
    int M, int N, int K)
{
    __shared__ __nv_bfloat16 Ah[64][40], Al[64][40], Bh[64][40], Bl[64][40];

    const int tid = threadIdx.x, warp = tid >> 5, lane = tid & 31;
    const int wm = warp >> 1, wn = warp & 1;
    const int bm = blockIdx.y * 64, bn = blockIdx.x * 64;
    const int g = lane >> 2, tg = lane & 3;

    float acc[2][4][4] = {};

    for (int k0 = 0; k0 < K; k0 += 32) {
        __syncthreads();
#pragma unroll
        for (int j = 0; j < 4; j++) {
            int idx = tid + j * 128;        // 0..511
            int r = idx >> 3, c = idx & 7;  // 64 rows x 8 float4
            float4 va = *(const float4*)&A[(size_t)(bm + r) * K + k0 + c * 4];
            float4 vb = *(const float4*)&B[(size_t)(bn + r) * K + k0 + c * 4];
            uint2 h, l;
            split4(va, h, l);
            *(uint2*)&Ah[r][c * 4] = h;
            *(uint2*)&Al[r][c * 4] = l;
            split4(vb, h, l);
            *(uint2*)&Bh[r][c * 4] = h;
            *(uint2*)&Bl[r][c * 4] = l;
        }
        __syncthreads();

#pragma unroll
        for (int ks = 0; ks < 2; ks++) {
            uint32_t af[2][2][4];   // [mi][hl][4]
            uint32_t bfr[4][2][2];  // [nj][hl][2]
            {
                int tile = lane >> 3;
#pragma unroll
                for (int mi = 0; mi < 2; mi++) {
                    int r = wm * 32 + mi * 16 + (lane & 7) + (tile & 1) * 8;
                    int kc = ks * 16 + (tile >> 1) * 8;
                    ldmx4(af[mi][0], smem_u32(&Ah[r][kc]));
                    ldmx4(af[mi][1], smem_u32(&Al[r][kc]));
                }
                int njo = lane >> 4, kh = (lane >> 3) & 1;
#pragma unroll
                for (int njp = 0; njp < 2; njp++) {
                    int r = wn * 32 + (njp * 2 + njo) * 8 + (lane & 7);
                    int kc = ks * 16 + kh * 8;
                    uint32_t t4[4];
                    ldmx4(t4, smem_u32(&Bh[r][kc]));
                    bfr[njp * 2][0][0] = t4[0]; bfr[njp * 2][0][1] = t4[1];
                    bfr[njp * 2 + 1][0][0] = t4[2]; bfr[njp * 2 + 1][0][1] = t4[3];
                    ldmx4(t4, smem_u32(&Bl[r][kc]));
                    bfr[njp * 2][1][0] = t4[0]; bfr[njp * 2][1][1] = t4[1];
                    bfr[njp * 2 + 1][1][0] = t4[2]; bfr[njp * 2 + 1][1][1] = t4[3];
                }
            }
#pragma unroll
            for (int mi = 0; mi < 2; mi++)
#pragma unroll
                for (int nj = 0; nj < 4; nj++) {
                    mma16816(acc[mi][nj], af[mi][0], bfr[nj][0]);  // hi*hi
                    mma16816(acc[mi][nj], af[mi][0], bfr[nj][1]);  // hi*lo
                    mma16816(acc[mi][nj], af[mi][1], bfr[nj][0]);  // lo*hi
                }
        }
    }

#pragma unroll
    for (int mi = 0; mi < 2; mi++)
#pragma unroll
        for (int nj = 0; nj < 4; nj++) {
            int r0 = bm + wm * 32 + mi * 16 + g;
            int cc = bn + wn * 32 + nj * 8 + tg * 2;
            float c0 = acc[mi][nj][0], c1 = acc[mi][nj][1];
            float c2 = acc[mi][nj][2], c3 = acc[mi][nj][3];
            if (SPLIT_OUT) {
                uint32_t h, l;
                split2(c0, c1, h, l);
                *(uint32_t*)&Chi[(size_t)r0 * N + cc] = h;
                *(uint32_t*)&Clo[(size_t)r0 * N + cc] = l;
                split2(c2, c3, h, l);
                *(uint32_t*)&Chi[(size_t)(r0 + 8) * N + cc] = h;
                *(uint32_t*)&Clo[(size_t)(r0 + 8) * N + cc] = l;
            } else {
                float2 rv = *(const float2*)&R[(size_t)r0 * N + cc];
                *(float2*)&C[(size_t)r0 * N + cc] = make_float2(c0 + rv.x, c1 + rv.y);
                rv = *(const float2*)&R[(size_t)(r0 + 8) * N + cc];
                *(float2*)&C[(size_t)(r0 + 8) * N + cc] = make_float2(c2 + rv.x, c3 + rv.y);
            }
        }
}

// ---------------------------------------------------------------------------
// Flash attention with bf16-split mma.
// grid (NT/64, NH), 128 threads (4 warps). Warp w: query rows w*16..+15.
// Q fragments live in registers across the whole key loop.
// ---------------------------------------------------------------------------
__global__ __launch_bounds__(128) void flash_mma(
    const __nv_bfloat16* __restrict__ Qh, const __nv_bfloat16* __restrict__ Ql,
    const __nv_bfloat16* __restrict__ Kh, const __nv_bfloat16* __restrict__ Kl,
    const __nv_bfloat16* __restrict__ Vh, const __nv_bfloat16* __restrict__ Vl,
    float* __restrict__ O)
{
    __shared__ __nv_bfloat16 sKh[64][72], sKl[64][72], sVh[64][72], sVl[64][72];

    const int h = blockIdx.y, q0 = blockIdx.x * 64;
    const int tid = threadIdx.x, warp = tid >> 5, lane = tid & 31;
    const int g = lane >> 2, tg = lane & 3;

    // ---- stage Q tile, load Q fragments (kept in regs all loop)
    {
        size_t base = (size_t)q0 * FEAT + h * DH;
#pragma unroll
        for (int j = 0; j < 4; j++) {
            int idx = tid + j * 128;
            int r = idx >> 3, c = idx & 7;
            *(uint4*)&sKh[r][c * 8] = *(const uint4*)&Qh[base + (size_t)r * FEAT + c * 8];
            *(uint4*)&sKl[r][c * 8] = *(const uint4*)&Ql[base + (size_t)r * FEAT + c * 8];
        }
    }
    __syncthreads();
    uint32_t qf[4][2][4];  // [ks][hl][4]
    {
        int tile = lane >> 3;
        int r = warp * 16 + (lane & 7) + (tile & 1) * 8;
#pragma unroll
        for (int ks = 0; ks < 4; ks++) {
            int kc = ks * 16 + (tile >> 1) * 8;
            ldmx4(qf[ks][0], smem_u32(&sKh[r][kc]));
            ldmx4(qf[ks][1], smem_u32(&sKl[r][kc]));
        }
    }

    float m0 = -1e30f, m1 = -1e30f, l0 = 0.f, l1 = 0.f;
    float o[8][4] = {};

    for (int kt = 0; kt < NT; kt += 64) {
        __syncthreads();
        {
            size_t base = (size_t)kt * FEAT + h * DH;
#pragma unroll
            for (int j = 0; j < 4; j++) {
                int idx = tid + j * 128;
                int r = idx >> 3, c = idx & 7;
                size_t goff = base + (size_t)r * FEAT + c * 8;
                *(uint4*)&sKh[r][c * 8] = *(const uint4*)&Kh[goff];
                *(uint4*)&sKl[r][c * 8] = *(const uint4*)&Kl[goff];
                *(uint4*)&sVh[r][c * 8] = *(const uint4*)&Vh[goff];
                *(uint4*)&sVl[r][c * 8] = *(const uint4*)&Vl[goff];
            }
        }
        __syncthreads();

        // ---- S = Q K^T (64 queries x 64 keys per warp-slice 16x64)
        float s[8][4] = {};
#pragma unroll
        for (int ks = 0; ks < 4; ks++) {
            uint32_t kb[8][2][2];  // [nj][hl][2]
            int njo = lane >> 4, kh = (lane >> 3) & 1;
#pragma unroll
            for (int njp = 0; njp < 4; njp++) {
                int r = njp * 16 + njo * 8 + (lane & 7);
                int kc = ks * 16 + kh * 8;
                uint32_t t4[4];
                ldmx4(t4, smem_u32(&sKh[r][kc]));
                kb[njp * 2][0][0] = t4[0]; kb[njp * 2][0][1] = t4[1];
                kb[njp * 2 + 1][0][0] = t4[2]; kb[njp * 2 + 1][0][1] = t4[3];
                ldmx4(t4, smem_u32(&sKl[r][kc]));
                kb[njp * 2][1][0] = t4[0]; kb[njp * 2][1][1] = t4[1];
                kb[njp * 2 + 1][1][0] = t4[2]; kb[njp * 2 + 1][1][1] = t4[3];
            }
#pragma unroll
            for (int nj = 0; nj < 8; nj++) {
                mma16816(s[nj], qf[ks][0], kb[nj][0]);
                mma16816(s[nj], qf[ks][0], kb[nj][1]);
                mma16816(s[nj], qf[ks][1], kb[nj][0]);
            }
        }

        // ---- online softmax (rows g and g+8; reduce over 4-lane groups)
        float mx0 = -1e30f, mx1 = -1e30f;
#pragma unroll
        for (int nj = 0; nj < 8; nj++) {
            s[nj][0] *= 0.125f; s[nj][1] *= 0.125f;
            s[nj][2] *= 0.125f; s[nj][3] *= 0.125f;
            mx0 = fmaxf(mx0, fmaxf(s[nj][0], s[nj][1]));
            mx1 = fmaxf(mx1, fmaxf(s[nj][2], s[nj][3]));
        }
        mx0 = fmaxf(mx0, __shfl_xor_sync(0xffffffffu, mx0, 1));
        mx0 = fmaxf(mx0, __shfl_xor_sync(0xffffffffu, mx0, 2));
        mx1 = fmaxf(mx1, __shfl_xor_sync(0xffffffffu, mx1, 1));
        mx1 = fmaxf(mx1, __shfl_xor_sync(0xffffffffu, mx1, 2));
        float nm0 = fmaxf(m0, mx0), nm1 = fmaxf(m1, mx1);
        float cr0 = __expf(m0 - nm0), cr1 = __expf(m1 - nm1);
        m0 = nm0; m1 = nm1;
        float rs0 = 0.f, rs1 = 0.f;
#pragma unroll
        for (int nj = 0; nj < 8; nj++) {
            s[nj][0] = __expf(s[nj][0] - nm0);
            s[nj][1] = __expf(s[nj][1] - nm0);
            s[nj][2] = __expf(s[nj][2] - nm1);
            s[nj][3] = __expf(s[nj][3] - nm1);
            rs0 += s[nj][0] + s[nj][1];
            rs1 += s[nj][2] + s[nj][3];
        }
        rs0 += __shfl_xor_sync(0xffffffffu, rs0, 1);
        rs0 += __shfl_xor_sync(0xffffffffu, rs0, 2);
        rs1 += __shfl_xor_sync(0xffffffffu, rs1, 1);
        rs1 += __shfl_xor_sync(0xffffffffu, rs1, 2);
        l0 = l0 * cr0 + rs0;
        l1 = l1 * cr1 + rs1;
#pragma unroll
        for (int nj = 0; nj < 8; nj++) {
            o[nj][0] *= cr0; o[nj][1] *= cr0;
            o[nj][2] *= cr1; o[nj][3] *= cr1;
        }

        // ---- pack P (C-frag -> A-frag identity), split hi/lo in registers
        uint32_t ph[4][4], pl[4][4];
#pragma unroll
        for (int j = 0; j < 4; j++) {
            split2(s[2 * j][0], s[2 * j][1], ph[j][0], pl[j][0]);
            split2(s[2 * j][2], s[2 * j][3], ph[j][1], pl[j][1]);
            split2(s[2 * j + 1][0], s[2 * j + 1][1], ph[j][2], pl[j][2]);
            split2(s[2 * j + 1][2], s[2 * j + 1][3], ph[j][3], pl[j][3]);
        }

        // ---- O += P V
#pragma unroll
        for (int j = 0; j < 4; j++) {
            uint32_t vbh[8][2], vbl[8][2];
            int njo = lane >> 4, tokh = (lane >> 3) & 1;
            int r = j * 16 + tokh * 8 + (lane & 7);
#pragma unroll
            for (int njp = 0; njp < 4; njp++) {
                int c = (njp * 2 + njo) * 8;
                uint32_t t4[4];
                ldmx4t(t4, smem_u32(&sVh[r][c]));
                vbh[njp * 2][0] = t4[0]; vbh[njp * 2][1] = t4[1];
                vbh[njp * 2 + 1][0] = t4[2]; vbh[njp * 2 + 1][1] = t4[3];
                ldmx4t(t4, smem_u32(&sVl[r][c]));
                vbl[njp * 2][0] = t4[0]; vbl[njp * 2][1] = t4[1];
                vbl[njp * 2 + 1][0] = t4[2]; vbl[njp * 2 + 1][1] = t4[3];
            }
#pragma unroll
            for (int nd = 0; nd < 8; nd++) {
                mma16816(o[nd], ph[j], vbh[nd]);
                mma16816(o[nd], ph[j], vbl[nd]);
                mma16816(o[nd], pl[j], vbh[nd]);
            }
        }
    }

    // ---- normalize + store
    float i0 = 1.0f / l0, i1 = 1.0f / l1;
    int r0 = q0 + warp * 16 + g;
#pragma unroll
    for (int nd = 0; nd < 8; nd++) {
        int col = h * DH + nd * 8 + tg * 2;
        *(float2*)&O[(size_t)r0 * FEAT + col] = make_float2(o[nd][0] * i0, o[nd][1] * i0);
        *(float2*)&O[(size_t)(r0 + 8) * FEAT + col] = make_float2(o[nd][2] * i1, o[nd][3] * i1);
    }
}

// ---------------------------------------------------------------------------
// Row LayerNorm (unchanged from R1)
// ---------------------------------------------------------------------------
__global__ __launch_bounds__(256) void ln_kernel(const float* __restrict__ Y,
                                                 const float* __restrict__ gamma,
                                                 const float* __restrict__ beta,
                                                 float* __restrict__ out)
{
    int row = blockIdx.x;
    const float* y = Y + (size_t)row * FEAT;
    int tid = threadIdx.x, warp = tid >> 5, lane = tid & 31;

    float v[3];
    float s = 0.f, ss = 0.f;
#pragma unroll
    for (int i = 0; i < 3; i++) {
        v[i] = y[tid + i * 256];
        s += v[i];
        ss += v[i] * v[i];
    }
#pragma unroll
    for (int o = 16; o; o >>= 1) {
        s  += __shfl_xor_sync(0xffffffffu, s, o);
        ss += __shfl_xor_sync(0xffffffffu, ss, o);
    }
    __shared__ float rs[8], rss[8];
    if (lane == 0) { rs[warp] = s; rss[warp] = ss; }
    __syncthreads();
    if (warp == 0) {
        float a = (lane < 8) ? rs[lane] : 0.f;
        float b = (lane < 8) ? rss[lane] : 0.f;
#pragma unroll
        for (int o = 4; o; o >>= 1) {
            a += __shfl_xor_sync(0xffffffffu, a, o);
            b += __shfl_xor_sync(0xffffffffu, b, o);
        }
        if (lane == 0) { rs[0] = a; rss[0] = b; }
    }
    __syncthreads();

    float mu = rs[0] * (1.0f / FEAT);
    float var = rss[0] * (1.0f / FEAT) - mu * mu;
    float rstd = rsqrtf(var + 1e-12f);
#pragma unroll
    for (int i = 0; i < 3; i++) {
        int c = tid + i * 256;
        out[(size_t)row * FEAT + c] = (v[i] - mu) * rstd * gamma[c] + beta[c];
    }
}

// ---------------------------------------------------------------------------

extern "C" void kernel_launch(void* const* d_in, const int* in_sizes, int n_in,
                              void* d_out, int out_size)
{
    const float* x     = (const float*)d_in[0];
    const float* Wq    = (const float*)d_in[1];
    const float* Wk    = (const float*)d_in[2];
    const float* Wv    = (const float*)d_in[3];
    const float* Wo    = (const float*)d_in[4];
    const float* gamma = (const float*)d_in[5];
    const float* beta  = (const float*)d_in[6];
    float* out = (float*)d_out;

    __nv_bfloat16 *pQh, *pQl, *pKh, *pKl, *pVh, *pVl;
    float *pA, *pY;
    cudaGetSymbolAddress((void**)&pQh, g_Qh);
    cudaGetSymbolAddress((void**)&pQl, g_Ql);
    cudaGetSymbolAddress((void**)&pKh, g_Kh);
    cudaGetSymbolAddress((void**)&pKl, g_Kl);
    cudaGetSymbolAddress((void**)&pVh, g_Vh);
    cudaGetSymbolAddress((void**)&pVl, g_Vl);
    cudaGetSymbolAddress((void**)&pA, g_A);
    cudaGetSymbolAddress((void**)&pY, g_Y);

    dim3 gg(FEAT / 64, NT / 64);  // (12, 32)
    gemm_mma<true><<<gg, 128>>>(x, Wq, nullptr, nullptr, pQh, pQl, NT, FEAT, FEAT);
    gemm_mma<true><<<gg, 128>>>(x, Wk, nullptr, nullptr, pKh, pKl, NT, FEAT, FEAT);
    gemm_mma<true><<<gg, 128>>>(x, Wv, nullptr, nullptr, pVh, pVl, NT, FEAT, FEAT);

    flash_mma<<<dim3(NT / 64, NH), 128>>>(pQh, pQl, pKh, pKl, pVh, pVl, pA);

    gemm_mma<false><<<gg, 128>>>(pA, Wo, x, pY, nullptr, nullptr, NT, FEAT, FEAT);

    ln_kernel<<<NT, 256>>>(pY, gamma, beta, out);
}

// round 7
// speedup vs baseline: 3.5535x; 1.1888x over previous
#include <cuda_runtime.h>
#include <cuda_bf16.h>
#include <cstdint>

#define NT   2048
#define FEAT 768
#define NH   12
#define DH   64

// Scratch (device globals; no allocation allowed)
__device__ __nv_bfloat16 g_Qh[NT * FEAT];
__device__ __nv_bfloat16 g_Ql[NT * FEAT];
__device__ __nv_bfloat16 g_Kh[NT * FEAT];
__device__ __nv_bfloat16 g_Kl[NT * FEAT];
__device__ __nv_bfloat16 g_Vh[NT * FEAT];
__device__ __nv_bfloat16 g_Vl[NT * FEAT];
__device__ float g_A[NT * FEAT];
__device__ float g_Y[NT * FEAT];

// ---------------------------------------------------------------------------
// PTX helpers
// ---------------------------------------------------------------------------
__device__ __forceinline__ uint32_t smem_u32(const void* p) {
    uint32_t a;
    asm("{ .reg .u64 t; cvta.to.shared.u64 t, %1; cvt.u32.u64 %0, t; }" : "=r"(a) : "l"(p));
    return a;
}
__device__ __forceinline__ void ldmx4(uint32_t* r, uint32_t addr) {
    asm volatile("ldmatrix.sync.aligned.m8n8.x4.shared.b16 {%0,%1,%2,%3}, [%4];"
                 : "=r"(r[0]), "=r"(r[1]), "=r"(r[2]), "=r"(r[3]) : "r"(addr));
}
__device__ __forceinline__ void ldmx4t(uint32_t* r, uint32_t addr) {
    asm volatile("ldmatrix.sync.aligned.m8n8.x4.trans.shared.b16 {%0,%1,%2,%3}, [%4];"
                 : "=r"(r[0]), "=r"(r[1]), "=r"(r[2]), "=r"(r[3]) : "r"(addr));
}
__device__ __forceinline__ void mma16816(float* c, const uint32_t* a, const uint32_t* b) {
    asm volatile(
        "mma.sync.aligned.m16n8k16.row.col.f32.bf16.bf16.f32 "
        "{%0,%1,%2,%3}, {%4,%5,%6,%7}, {%8,%9}, {%0,%1,%2,%3};"
        : "+f"(c[0]), "+f"(c[1]), "+f"(c[2]), "+f"(c[3])
        : "r"(a[0]), "r"(a[1]), "r"(a[2]), "r"(a[3]), "r"(b[0]), "r"(b[1]));
}
__device__ __forceinline__ void cpa16(uint32_t saddr, const void* g) {
    asm volatile("cp.async.ca.shared.global [%0], [%1], 16;" :: "r"(saddr), "l"(g) : "memory");
}
#define CPA_COMMIT() asm volatile("cp.async.commit_group;" ::: "memory")
#define CPA_WAIT0()  asm volatile("cp.async.wait_group 0;" ::: "memory")

// split fp32 -> (hi, lo) bf16 packed pairs
__device__ __forceinline__ uint32_t pack2(__nv_bfloat16 a, __nv_bfloat16 b) {
    return (uint32_t)__bfloat16_as_ushort(a) | ((uint32_t)__bfloat16_as_ushort(b) << 16);
}
__device__ __forceinline__ void split2(float x, float y, uint32_t& h, uint32_t& l) {
    __nv_bfloat16 hx = __float2bfloat16(x), hy = __float2bfloat16(y);
    __nv_bfloat16 lx = __float2bfloat16(x - __bfloat162float(hx));
    __nv_bfloat16 ly = __float2bfloat16(y - __bfloat162float(hy));
    h = pack2(hx, hy);
    l = pack2(lx, ly);
}
__device__ __forceinline__ void split4(float4 v, uint2& h, uint2& l) {
    uint32_t h0, l0, h1, l1;
    split2(v.x, v.y, h0, l0);
    split2(v.z, v.w, h1, l1);
    h = make_uint2(h0, h1);
    l = make_uint2(l0, l1);
}

// ---------------------------------------------------------------------------
// GEMM: C[m][n] = sum_k A[m][k]*B[n][k] via bf16-split mma (3 products).
// Block 64x64, BK=32, 128 threads, double-buffered smem stages, pipelined LDG.
// SPLIT: QKV fused (grid.x = 3*12, selects matrix), bf16 hi/lo outputs.
// else:  single B, fp32 C = A@B^T + R residual.
// ---------------------------------------------------------------------------
template <bool SPLIT>
__global__ __launch_bounds__(128) void gemm_mma(
    const float* __restrict__ A,
    const float* __restrict__ B0, const float* __restrict__ B1,
    const float* __restrict__ B2,
    float* __restrict__ C, const float* __restrict__ R,
    __nv_bfloat16* __restrict__ H0, __nv_bfloat16* __restrict__ L0,
    __nv_bfloat16* __restrict__ H1, __nv_bfloat16* __restrict__ L1,
    __nv_bfloat16* __restrict__ H2, __nv_bfloat16* __restrict__ L2)
{
    __shared__ __nv_bfloat16 Ah[2][64][40], Al[2][64][40], Bh[2][64][40], Bl[2][64][40];

    const int tid = threadIdx.x, warp = tid >> 5, lane = tid & 31;
    const int wm = warp >> 1, wn = warp & 1;
    const int bm = blockIdx.y * 64;
    const int g = lane >> 2, tg = lane & 3;

    int bn;
    const float* B;
    __nv_bfloat16 *H = nullptr, *L = nullptr;
    if (SPLIT) {
        int mat = blockIdx.x / 12;
        bn = (blockIdx.x % 12) * 64;
        B = (mat == 0) ? B0 : (mat == 1) ? B1 : B2;
        H = (mat == 0) ? H0 : (mat == 1) ? H1 : H2;
        L = (mat == 0) ? L0 : (mat == 1) ? L1 : L2;
    } else {
        bn = blockIdx.x * 64;
        B = B0;
    }

    float acc[2][4][4] = {};
    float4 ra[4], rb[4];

    auto ldg_chunk = [&](int c) {
        int k0 = c * 32;
#pragma unroll
        for (int j = 0; j < 4; j++) {
            int idx = tid + j * 128;
            int r = idx >> 3, cc = idx & 7;
            ra[j] = *(const float4*)&A[(size_t)(bm + r) * FEAT + k0 + cc * 4];
            rb[j] = *(const float4*)&B[(size_t)(bn + r) * FEAT + k0 + cc * 4];
        }
    };
    auto sts_chunk = [&](int s) {
#pragma unroll
        for (int j = 0; j < 4; j++) {
            int idx = tid + j * 128;
            int r = idx >> 3, cc = idx & 7;
            uint2 h, l;
            split4(ra[j], h, l);
            *(uint2*)&Ah[s][r][cc * 4] = h;
            *(uint2*)&Al[s][r][cc * 4] = l;
            split4(rb[j], h, l);
            *(uint2*)&Bh[s][r][cc * 4] = h;
            *(uint2*)&Bl[s][r][cc * 4] = l;
        }
    };

    ldg_chunk(0);
    sts_chunk(0);

    const int NC = FEAT / 32;  // 24
#pragma unroll 1
    for (int c = 0; c < NC; c++) {
        __syncthreads();
        const int s = c & 1;
        if (c + 1 < NC) ldg_chunk(c + 1);  // in-flight during compute

#pragma unroll
        for (int ks = 0; ks < 2; ks++) {
            uint32_t af[2][2][4];
            uint32_t bfr[4][2][2];
            {
                int tile = lane >> 3;
#pragma unroll
                for (int mi = 0; mi < 2; mi++) {
                    int r = wm * 32 + mi * 16 + (lane & 7) + (tile & 1) * 8;
                    int kc = ks * 16 + (tile >> 1) * 8;
                    ldmx4(af[mi][0], smem_u32(&Ah[s][r][kc]));
                    ldmx4(af[mi][1], smem_u32(&Al[s][r][kc]));
                }
                int njo = lane >> 4, kh = (lane >> 3) & 1;
#pragma unroll
                for (int njp = 0; njp < 2; njp++) {
                    int r = wn * 32 + (njp * 2 + njo) * 8 + (lane & 7);
                    int kc = ks * 16 + kh * 8;
                    uint32_t t4[4];
                    ldmx4(t4, smem_u32(&Bh[s][r][kc]));
                    bfr[njp * 2][0][0] = t4[0]; bfr[njp * 2][0][1] = t4[1];
                    bfr[njp * 2 + 1][0][0] = t4[2]; bfr[njp * 2 + 1][0][1] = t4[3];
                    ldmx4(t4, smem_u32(&Bl[s][r][kc]));
                    bfr[njp * 2][1][0] = t4[0]; bfr[njp * 2][1][1] = t4[1];
                    bfr[njp * 2 + 1][1][0] = t4[2]; bfr[njp * 2 + 1][1][1] = t4[3];
                }
            }
#pragma unroll
            for (int mi = 0; mi < 2; mi++)
#pragma unroll
                for (int nj = 0; nj < 4; nj++) {
                    mma16816(acc[mi][nj], af[mi][0], bfr[nj][0]);  // hi*hi
                    mma16816(acc[mi][nj], af[mi][0], bfr[nj][1]);  // hi*lo
                    mma16816(acc[mi][nj], af[mi][1], bfr[nj][0]);  // lo*hi
                }
        }

        if (c + 1 < NC) sts_chunk((c + 1) & 1);  // other stage; safe: all passed sync
    }

#pragma unroll
    for (int mi = 0; mi < 2; mi++)
#pragma unroll
        for (int nj = 0; nj < 4; nj++) {
            int r0 = bm + wm * 32 + mi * 16 + g;
            int cc = bn + wn * 32 + nj * 8 + tg * 2;
            float c0 = acc[mi][nj][0], c1 = acc[mi][nj][1];
            float c2 = acc[mi][nj][2], c3 = acc[mi][nj][3];
            if (SPLIT) {
                uint32_t h, l;
                split2(c0, c1, h, l);
                *(uint32_t*)&H[(size_t)r0 * FEAT + cc] = h;
                *(uint32_t*)&L[(size_t)r0 * FEAT + cc] = l;
                split2(c2, c3, h, l);
                *(uint32_t*)&H[(size_t)(r0 + 8) * FEAT + cc] = h;
                *(uint32_t*)&L[(size_t)(r0 + 8) * FEAT + cc] = l;
            } else {
                float2 rv = *(const float2*)&R[(size_t)r0 * FEAT + cc];
                *(float2*)&C[(size_t)r0 * FEAT + cc] = make_float2(c0 + rv.x, c1 + rv.y);
                rv = *(const float2*)&R[(size_t)(r0 + 8) * FEAT + cc];
                *(float2*)&C[(size_t)(r0 + 8) * FEAT + cc] = make_float2(c2 + rv.x, c3 + rv.y);
            }
        }
}

// ---------------------------------------------------------------------------
// Flash attention, bf16-split mma, cp.async double-buffered K/V tiles.
// grid (NT/64, NH), 128 threads (4 warps). Warp w: query rows w*16..+15.
// Dynamic smem: 2 stages x { Kh, Kl, Vh, Vl : 64 rows x 72 bf16 (144B pitch) }.
// Stage stride 36864B; array offsets 0 / 9216 / 18432 / 27648.
// ---------------------------------------------------------------------------
#define FL_STAGE   36864
#define FL_PITCH   144
#define FL_SMEM    (2 * FL_STAGE)

__global__ __launch_bounds__(128) void flash_mma(
    const __nv_bfloat16* __restrict__ Qh, const __nv_bfloat16* __restrict__ Ql,
    const __nv_bfloat16* __restrict__ Kh, const __nv_bfloat16* __restrict__ Kl,
    const __nv_bfloat16* __restrict__ Vh, const __nv_bfloat16* __restrict__ Vl,
    float* __restrict__ O)
{
    extern __shared__ char sm[];
    const uint32_t sb = smem_u32(sm);

    const int h = blockIdx.y, q0 = blockIdx.x * 64;
    const int tid = threadIdx.x, warp = tid >> 5, lane = tid & 31;
    const int g = lane >> 2, tg = lane & 3;

    auto prefetch = [&](int t, int st) {
        size_t base = (size_t)(t * 64) * FEAT + h * DH;
        uint32_t s0 = sb + st * FL_STAGE;
#pragma unroll
        for (int j = 0; j < 4; j++) {
            int idx = tid + j * 128;
            int r = idx >> 3, c8 = idx & 7;
            size_t go = base + (size_t)r * FEAT + c8 * 8;
            uint32_t so = s0 + r * FL_PITCH + c8 * 16;
            cpa16(so,         &Kh[go]);
            cpa16(so +  9216, &Kl[go]);
            cpa16(so + 18432, &Vh[go]);
            cpa16(so + 27648, &Vl[go]);
        }
        CPA_COMMIT();
    };

    // prefetch tile 0 into stage 0 (async, overlaps Q staging below)
    prefetch(0, 0);

    // stage Q into stage-1 Kh/Kl regions
    {
        size_t base = (size_t)q0 * FEAT + h * DH;
#pragma unroll
        for (int j = 0; j < 4; j++) {
            int idx = tid + j * 128;
            int r = idx >> 3, c8 = idx & 7;
            size_t go = base + (size_t)r * FEAT + c8 * 8;
            *(uint4*)(sm + FL_STAGE + r * FL_PITCH + c8 * 16)        = *(const uint4*)&Qh[go];
            *(uint4*)(sm + FL_STAGE + 9216 + r * FL_PITCH + c8 * 16) = *(const uint4*)&Ql[go];
        }
    }
    __syncthreads();

    uint32_t qf[4][2][4];
    {
        int tile = lane >> 3;
        int r = warp * 16 + (lane & 7) + (tile & 1) * 8;
#pragma unroll
        for (int ks = 0; ks < 4; ks++) {
            int kc = ks * 16 + (tile >> 1) * 8;
            uint32_t a = sb + FL_STAGE + r * FL_PITCH + kc * 2;
            ldmx4(qf[ks][0], a);
            ldmx4(qf[ks][1], a + 9216);
        }
    }

    float m0 = -1e30f, m1 = -1e30f, l0 = 0.f, l1 = 0.f;
    float o[8][4] = {};

#pragma unroll 1
    for (int t = 0; t < NT / 64; t++) {
        CPA_WAIT0();
        __syncthreads();                       // tile t visible; qf extraction done (t==0)
        if (t + 1 < NT / 64) prefetch(t + 1, (t + 1) & 1);
        const uint32_t s0 = sb + (t & 1) * FL_STAGE;

        // ---- S = Q K^T
        float s[8][4] = {};
#pragma unroll
        for (int ks = 0; ks < 4; ks++) {
            uint32_t kb[8][2][2];
            int njo = lane >> 4, kh = (lane >> 3) & 1;
#pragma unroll
            for (int njp = 0; njp < 4; njp++) {
                int r = njp * 16 + njo * 8 + (lane & 7);
                int kc = ks * 16 + kh * 8;
                uint32_t a = s0 + r * FL_PITCH + kc * 2;
                uint32_t t4[4];
                ldmx4(t4, a);
                kb[njp * 2][0][0] = t4[0]; kb[njp * 2][0][1] = t4[1];
                kb[njp * 2 + 1][0][0] = t4[2]; kb[njp * 2 + 1][0][1] = t4[3];
                ldmx4(t4, a + 9216);
                kb[njp * 2][1][0] = t4[0]; kb[njp * 2][1][1] = t4[1];
                kb[njp * 2 + 1][1][0] = t4[2]; kb[njp * 2 + 1][1][1] = t4[3];
            }
#pragma unroll
            for (int nj = 0; nj < 8; nj++) {
                mma16816(s[nj], qf[ks][0], kb[nj][0]);
                mma16816(s[nj], qf[ks][0], kb[nj][1]);
                mma16816(s[nj], qf[ks][1], kb[nj][0]);
            }
        }

        // ---- online softmax (rows g and g+8; reduce over 4-lane groups)
        float mx0 = -1e30f, mx1 = -1e30f;
#pragma unroll
        for (int nj = 0; nj < 8; nj++) {
            s[nj][0] *= 0.125f; s[nj][1] *= 0.125f;
            s[nj][2] *= 0.125f; s[nj][3] *= 0.125f;
            mx0 = fmaxf(mx0, fmaxf(s[nj][0], s[nj][1]));
            mx1 = fmaxf(mx1, fmaxf(s[nj][2], s[nj][3]));
        }
        mx0 = fmaxf(mx0, __shfl_xor_sync(0xffffffffu, mx0, 1));
        mx0 = fmaxf(mx0, __shfl_xor_sync(0xffffffffu, mx0, 2));
        mx1 = fmaxf(mx1, __shfl_xor_sync(0xffffffffu, mx1, 1));
        mx1 = fmaxf(mx1, __shfl_xor_sync(0xffffffffu, mx1, 2));
        float nm0 = fmaxf(m0, mx0), nm1 = fmaxf(m1, mx1);
        float cr0 = __expf(m0 - nm0), cr1 = __expf(m1 - nm1);
        m0 = nm0; m1 = nm1;
        float rs0 = 0.f, rs1 = 0.f;
#pragma unroll
        for (int nj = 0; nj < 8; nj++) {
            s[nj][0] = __expf(s[nj][0] - nm0);
            s[nj][1] = __expf(s[nj][1] - nm0);
            s[nj][2] = __expf(s[nj][2] - nm1);
            s[nj][3] = __expf(s[nj][3] - nm1);
            rs0 += s[nj][0] + s[nj][1];
            rs1 += s[nj][2] + s[nj][3];
        }
        rs0 += __shfl_xor_sync(0xffffffffu, rs0, 1);
        rs0 += __shfl_xor_sync(0xffffffffu, rs0, 2);
        rs1 += __shfl_xor_sync(0xffffffffu, rs1, 1);
        rs1 += __shfl_xor_sync(0xffffffffu, rs1, 2);
        l0 = l0 * cr0 + rs0;
        l1 = l1 * cr1 + rs1;
#pragma unroll
        for (int nj = 0; nj < 8; nj++) {
            o[nj][0] *= cr0; o[nj][1] *= cr0;
            o[nj][2] *= cr1; o[nj][3] *= cr1;
        }

        // ---- pack P (C-frag -> A-frag identity), split hi/lo in registers
        uint32_t pht[4][4], plt[4][4];
#pragma unroll
        for (int j = 0; j < 4; j++) {
            split2(s[2 * j][0], s[2 * j][1], pht[j][0], plt[j][0]);
            split2(s[2 * j][2], s[2 * j][3], pht[j][1], plt[j][1]);
            split2(s[2 * j + 1][0], s[2 * j + 1][1], pht[j][2], plt[j][2]);
            split2(s[2 * j + 1][2], s[2 * j + 1][3], pht[j][3], plt[j][3]);
        }

        // ---- O += P V
#pragma unroll
        for (int j = 0; j < 4; j++) {
            uint32_t vbh[8][2], vbl[8][2];
            int njo = lane >> 4, tokh = (lane >> 3) & 1;
            int r = j * 16 + tokh * 8 + (lane & 7);
#pragma unroll
            for (int njp = 0; njp < 4; njp++) {
                int c = (njp * 2 + njo) * 8;
                uint32_t a = s0 + 18432 + r * FL_PITCH + c * 2;
                uint32_t t4[4];
                ldmx4t(t4, a);
                vbh[njp * 2][0] = t4[0]; vbh[njp * 2][1] = t4[1];
                vbh[njp * 2 + 1][0] = t4[2]; vbh[njp * 2 + 1][1] = t4[3];
                ldmx4t(t4, a + 9216);
                vbl[njp * 2][0] = t4[0]; vbl[njp * 2][1] = t4[1];
                vbl[njp * 2 + 1][0] = t4[2]; vbl[njp * 2 + 1][1] = t4[3];
            }
#pragma unroll
            for (int nd = 0; nd < 8; nd++) {
                mma16816(o[nd], pht[j], vbh[nd]);
                mma16816(o[nd], pht[j], vbl[nd]);
                mma16816(o[nd], plt[j], vbh[nd]);
            }
        }
    }

    float i0 = 1.0f / l0, i1 = 1.0f / l1;
    int r0 = q0 + warp * 16 + g;
#pragma unroll
    for (int nd = 0; nd < 8; nd++) {
        int col = h * DH + nd * 8 + tg * 2;
        *(float2*)&O[(size_t)r0 * FEAT + col] = make_float2(o[nd][0] * i0, o[nd][1] * i0);
        *(float2*)&O[(size_t)(r0 + 8) * FEAT + col] = make_float2(o[nd][2] * i1, o[nd][3] * i1);
    }
}

// ---------------------------------------------------------------------------
// Row LayerNorm
// ---------------------------------------------------------------------------
__global__ __launch_bounds__(256) void ln_kernel(const float* __restrict__ Y,
                                                 const float* __restrict__ gamma,
                                                 const float* __restrict__ beta,
                                                 float* __restrict__ out)
{
    int row = blockIdx.x;
    const float* y = Y + (size_t)row * FEAT;
    int tid = threadIdx.x, warp = tid >> 5, lane = tid & 31;

    float v[3];
    float s = 0.f, ss = 0.f;
#pragma unroll
    for (int i = 0; i < 3; i++) {
        v[i] = y[tid + i * 256];
        s += v[i];
        ss += v[i] * v[i];
    }
#pragma unroll
    for (int o = 16; o; o >>= 1) {
        s  += __shfl_xor_sync(0xffffffffu, s, o);
        ss += __shfl_xor_sync(0xffffffffu, ss, o);
    }
    __shared__ float rs[8], rss[8];
    if (lane == 0) { rs[warp] = s; rss[warp] = ss; }
    __syncthreads();
    if (warp == 0) {
        float a = (lane < 8) ? rs[lane] : 0.f;
        float b = (lane < 8) ? rss[lane] : 0.f;
#pragma unroll
        for (int o = 4; o; o >>= 1) {
            a += __shfl_xor_sync(0xffffffffu, a, o);
            b += __shfl_xor_sync(0xffffffffu, b, o);
        }
        if (lane == 0) { rs[0] = a; rss[0] = b; }
    }
    __syncthreads();

    float mu = rs[0] * (1.0f / FEAT);
    float var = rss[0] * (1.0f / FEAT) - mu * mu;
    float rstd = rsqrtf(var + 1e-12f);
#pragma unroll
    for (int i = 0; i < 3; i++) {
        int c = tid + i * 256;
        out[(size_t)row * FEAT + c] = (v[i] - mu) * rstd * gamma[c] + beta[c];
    }
}

// ---------------------------------------------------------------------------

extern "C" void kernel_launch(void* const* d_in, const int* in_sizes, int n_in,
                              void* d_out, int out_size)
{
    const float* x     = (const float*)d_in[0];
    const float* Wq    = (const float*)d_in[1];
    const float* Wk    = (const float*)d_in[2];
    const float* Wv    = (const float*)d_in[3];
    const float* Wo    = (const float*)d_in[4];
    const float* gamma = (const float*)d_in[5];
    const float* beta  = (const float*)d_in[6];
    float* out = (float*)d_out;

    __nv_bfloat16 *pQh, *pQl, *pKh, *pKl, *pVh, *pVl;
    float *pA, *pY;
    cudaGetSymbolAddress((void**)&pQh, g_Qh);
    cudaGetSymbolAddress((void**)&pQl, g_Ql);
    cudaGetSymbolAddress((void**)&pKh, g_Kh);
    cudaGetSymbolAddress((void**)&pKl, g_Kl);
    cudaGetSymbolAddress((void**)&pVh, g_Vh);
    cudaGetSymbolAddress((void**)&pVl, g_Vl);
    cudaGetSymbolAddress((void**)&pA, g_A);
    cudaGetSymbolAddress((void**)&pY, g_Y);

    cudaFuncSetAttribute(flash_mma, cudaFuncAttributeMaxDynamicSharedMemorySize, FL_SMEM);

    // fused QKV projections
    gemm_mma<true><<<dim3(36, NT / 64), 128>>>(
        x, Wq, Wk, Wv, nullptr, nullptr, pQh, pQl, pKh, pKl, pVh, pVl);

    flash_mma<<<dim3(NT / 64, NH), 128, FL_SMEM>>>(pQh, pQl, pKh, pKl, pVh, pVl, pA);

    // output projection + residual
    gemm_mma<false><<<dim3(FEAT / 64, NT / 64), 128>>>(
        pA, Wo, nullptr, nullptr, pY, x, nullptr, nullptr, nullptr, nullptr, nullptr, nullptr);

    ln_kernel<<<NT, 256>>>(pY, gamma, beta, out);
}